// round 2
// baseline (speedup 1.0000x reference)
#include <cuda_runtime.h>

#define PI_D 3.141592653589793238462643383279502884
#define SCALING_F 0.008164965809277260f   // 1/sqrt(24*16*20^4/64^2) = 1/sqrt(15000)

// Compact l-major layout for m>=0 spectra:
//   per l: (l+1) rows (m = 0..l) x (2l+1) cols (ni = n+l).  Total NC = 5530.
#define NC 5530

// ---------------- scratch (device globals; no allocation allowed) ----------------
static __device__ double dd_df[41];                  // factorials
static __device__ double dd_wq[128];
static __device__ float  dd_ws2[128 * 400];          // [b][col]
static __device__ float2 dd_Fk[24 * 400];            // [p][col]
static __device__ float  dd_dinv[40 * NC];           // [b][cidx]  (2l+1)*d^l_{m,n}, m>=0
static __device__ float2 dd_XF[16 * 16 * 20 * 128];  // [(z*16+i)][m(0..19)][b]
static __device__ float2 dd_G[16 * 16 * 400];        // [(z*16+i)][col]
static __device__ float2 dd_Y[32 * 400 * 16];        // conj(y)*SCALING: [o][col][i]
static __device__ float2 dd_ZL[512 * NC];            // [(z*32+o)][cidx], m>=0 only
static __device__ float2 dd_tw40[40];                // e^{+2pi i t/40}
static __device__ float2 dd_tw128[128];              // e^{+2pi i t/128}

// ---------------- Wigner small-d via factorial-ratio recurrence (fp64) ----------------
__device__ double wigner_d_dev(int l, int m, int n, double beta) {
    double cb = cos(0.5 * beta), sb = sin(0.5 * beta);
    int s0 = (n - m) > 0 ? (n - m) : 0;
    int s1 = (l + n) < (l - m) ? (l + n) : (l - m);
    if (s1 < s0) return 0.0;
    double pref = sqrt(dd_df[l + m]) * sqrt(dd_df[l - m]) * sqrt(dd_df[l + n]) * sqrt(dd_df[l - n]);
    double t = pref / (dd_df[l + n - s0] * dd_df[s0] * dd_df[m - n + s0] * dd_df[l - m - s0]);
    int ec = 2 * l + n - m - 2 * s0;
    int es = m - n + 2 * s0;
    for (int k = 0; k < ec; k++) t *= cb;
    for (int k = 0; k < es; k++) t *= sb;
    if ((m - n + s0) & 1) t = -t;
    double v = t;
    double r2 = (sb * sb) / (cb * cb);
    for (int s = s0; s < s1; s++) {
        t *= -r2 * (double)((l + n - s) * (l - m - s)) / (double)((s + 1) * (m - n + s + 1));
        v += t;
    }
    return v;
}

__device__ __forceinline__ int col_to_l(int col) {
    int l = (int)sqrtf((float)col);
    while ((l + 1) * (l + 1) <= col) l++;
    while (l * l > col) l--;
    return l;
}

// decode compact cidx -> (l, m>=0, ni)
__device__ __forceinline__ void decode_c(int c, int& l, int& m, int& ni) {
    l = 0;
    while (c >= (l + 1) * (2 * l + 1)) { c -= (l + 1) * (2 * l + 1); l++; }
    int w = 2 * l + 1;
    m = c / w;
    ni = c - m * w;
}

// cum2(l) = sum_{j<l} (j+1)(2j+1)
__device__ __forceinline__ int cum2f(int l) {
    return (l - 1) * l * (2 * l - 1) / 3 + 3 * l * (l - 1) / 2 + l;
}

// ---------------- stage 0: tables ----------------
__global__ void k_setup() {
    int t = threadIdx.x;
    if (t < 41) {
        double f = 1.0;
        for (int k = 2; k <= t; k++) f *= (double)k;
        dd_df[t] = f;
    }
    if (t < 40) {
        double a = 2.0 * PI_D * t / 40.0;
        dd_tw40[t] = make_float2((float)cos(a), (float)sin(a));
    }
    if (t < 128) {
        double a = 2.0 * PI_D * t / 128.0;
        dd_tw128[t] = make_float2((float)cos(a), (float)sin(a));
        double th = PI_D * (2 * t + 1) / 256.0;
        double s = 0.0;
        for (int k = 0; k < 64; k++) s += sin((2.0 * k + 1.0) * th) / (2.0 * k + 1.0);
        dd_wq[t] = (2.0 / 64.0) * sin(th) * s;
    }
}

__global__ void k_ws2() {
    int idx = blockIdx.x * blockDim.x + threadIdx.x;
    if (idx >= 128 * 400) return;
    int b = idx / 400, col = idx - b * 400;
    int l = col_to_l(col);
    int m = col - l * l - l;
    double beta = PI_D * (2 * b + 1) / 256.0;
    dd_ws2[idx] = (float)(wigner_d_dev(l, m, 0, beta) * dd_wq[b]);
}

__global__ void k_Fk() {
    int idx = blockIdx.x * blockDim.x + threadIdx.x;
    if (idx >= 24 * 400) return;
    int p = idx / 400, col = idx - p * 400;
    int l = col_to_l(col);
    int m = col - l * l - l;
    double beta = (double)(p / 8 + 1) * PI_D / 24.0;
    double alpha = (double)(p % 8) * (PI_D / 4.0);
    double d = wigner_d_dev(l, m, 0, beta);
    dd_Fk[idx] = make_float2((float)(d * cos(m * alpha)), (float)(-d * sin(m * alpha)));
}

__global__ void k_dinv() {
    int idx = blockIdx.x * blockDim.x + threadIdx.x;
    if (idx >= 40 * NC) return;
    int b = idx / NC, c = idx - b * NC;
    int l, m, ni;
    decode_c(c, l, m, ni);
    double beta = PI_D * (2 * b + 1) / 80.0;
    dd_dinv[idx] = (float)((double)(2 * l + 1) * wigner_d_dev(l, m, ni - l, beta));
}

// ---------------- stage 1: alpha-DFT (20 non-negative bins), one block per (z,i) ----------------
__global__ void k_XF(const float* __restrict__ x) {
    __shared__ float2 twT[128 * 20];   // [a][m], e^{-2pi i m a/128} stored as (cos,-sin)
    __shared__ float  xs[12][129];     // padded rows
    int zi = blockIdx.x;
    int t = threadIdx.x;               // 256 threads
    for (int i = t; i < 128 * 20; i += 256) {
        int a = i / 20, mi = i - a * 20;
        float2 w = dd_tw128[(a * mi) & 127];
        twT[i] = make_float2(w.x, -w.y);
    }
    const float* xp = x + (size_t)zi * 128 * 128;
    for (int chunk = 0; chunk < 11; chunk++) {
        int b0 = chunk * 12;
        __syncthreads();
        for (int i = t; i < 12 * 128; i += 256) {
            int r = i >> 7, a = i & 127;
            if (b0 + r < 128) xs[r][a] = xp[(size_t)(b0 + r) * 128 + a];
        }
        __syncthreads();
        if (t < 240) {
            int r = t / 20, mi = t - r * 20;
            int b = b0 + r;
            if (b < 128) {
                float re = 0.f, im = 0.f;
                #pragma unroll 8
                for (int a = 0; a < 128; a++) {
                    float v = xs[r][a];
                    float2 w = twT[a * 20 + mi];
                    re += v * w.x;
                    im += v * w.y;
                }
                dd_XF[((size_t)zi * 20 + mi) * 128 + b] = make_float2(re, im);
            }
        }
    }
}

// ---------------- stage 2: S2 analysis (negative m via conjugate) ----------------
__global__ void k_G() {
    int idx = blockIdx.x * blockDim.x + threadIdx.x;
    if (idx >= 16 * 16 * 400) return;
    int zi = idx / 400, col = idx - zi * 400;
    int l = col_to_l(col);
    int m = col - l * l - l;
    int am = m < 0 ? -m : m;
    float sgn = m < 0 ? -1.f : 1.f;
    const float2* xf = &dd_XF[((size_t)zi * 20 + am) * 128];
    float re = 0.f, im = 0.f;
    #pragma unroll 4
    for (int b = 0; b < 128; b++) {
        float w = dd_ws2[b * 400 + col];
        float2 v = xf[b];
        re += w * v.x;
        im += w * v.y;
    }
    dd_G[idx] = make_float2(re, sgn * im);
}

// ---------------- stage 3: kernel spectrum (store conj * SCALING) ----------------
__global__ void k_Y(const float* __restrict__ ker) {
    int idx = blockIdx.x * blockDim.x + threadIdx.x;
    if (idx >= 32 * 400 * 16) return;
    int o = idx / 6400;
    int r = idx - o * 6400;
    int col = r / 16, i = r - col * 16;
    const float* kp = ker + ((size_t)i * 32 + o) * 24;
    float re = 0.f, im = 0.f;
    #pragma unroll
    for (int p = 0; p < 24; p++) {
        float2 f = dd_Fk[p * 400 + col];
        float kv = kp[p];
        re += kv * f.x;
        im += kv * f.y;
    }
    dd_Y[idx] = make_float2(SCALING_F * re, -SCALING_F * im);
}

// ---------------- stage 4: per-(z,o) SO(3) spectrum (m>=0 only) ----------------
__global__ void k_ZL() {
    extern __shared__ float2 smzl[];
    float2* Gs = smzl;            // 6400: [i][col] for this z
    float2* Ys = smzl + 6400;     // 6400: [col][i] for this o (already conj)
    int bi = blockIdx.x;
    int z = bi >> 5, o = bi & 31;
    int tid = threadIdx.x;
    for (int i = tid; i < 6400; i += blockDim.x) {
        Gs[i] = dd_G[z * 6400 + i];
        Ys[i] = dd_Y[o * 6400 + i];
    }
    __syncthreads();
    for (int cidx = tid; cidx < NC; cidx += blockDim.x) {
        int l, m, ni;
        decode_c(cidx, l, m, ni);
        int colm = l * l + l + m;      // m >= 0
        int coln = l * l + ni;
        float re = 0.f, im = 0.f;
        #pragma unroll
        for (int i = 0; i < 16; i++) {
            float2 a = Gs[i * 400 + colm];
            float2 yb = Ys[coln * 16 + i];
            re += a.x * yb.x - a.y * yb.y;
            im += a.x * yb.y + a.y * yb.x;
        }
        dd_ZL[(size_t)bi * NC + cidx] = make_float2(re, im);
    }
}

// ---------------- stage 5+6 fused: beta synthesis + Hermitian 2D inverse DFT ----------------
// grid = 512 (z,o) * 2 beta-halves; zl slice (m>=0) cached in SMEM.
__global__ void k_OUT(const float* __restrict__ bias, float* __restrict__ out) {
    extern __shared__ float2 sm[];
    float2* zls = sm;                  // NC = 5530
    float2* Ms  = sm + NC;             // 780 = 20*39  [m 0..19][nni 0..38]
    float2* Ts  = sm + NC + 780;       // 800 = 20*40  [m 0..19][g]
    float2* twl = sm + NC + 780 + 800; // 40
    int bi = blockIdx.x >> 1;
    int half = blockIdx.x & 1;
    int o = bi & 31;
    int tid = threadIdx.x;
    for (int i = tid; i < NC; i += blockDim.x) zls[i] = dd_ZL[(size_t)bi * NC + i];
    if (tid < 40) twl[tid] = dd_tw40[tid];
    float bv = bias[o];
    __syncthreads();
    float* outp = out + (size_t)bi * 64000;

    int bbeg = half * 20, bend = bbeg + 20;
    for (int b = bbeg; b < bend; b++) {
        const float* dv = &dd_dinv[b * NC];
        // M[m,n] = sum_l zl[l,m,n] * dinv[l,b,m,n]   (m >= 0)
        for (int p = tid; p < 780; p += blockDim.x) {
            int m = p / 39, nni = p - m * 39;
            int n = nni - 19;
            int an = n < 0 ? -n : n;
            int lmin = m > an ? m : an;
            int cum = cum2f(lmin);
            float re = 0.f, im = 0.f;
            for (int l = lmin; l < 20; l++) {
                int w = 2 * l + 1;
                int cidx = cum + m * w + (n + l);
                float d = dv[cidx];
                float2 zv = zls[cidx];
                re += zv.x * d;
                im += zv.y * d;
                cum += (l + 1) * w;
            }
            Ms[p] = make_float2(re, im);
        }
        __syncthreads();
        // T[m,g] = sum_n M[m,n] e^{+2pi i n g/40}   (m = 0..19)
        for (int p = tid; p < 800; p += blockDim.x) {
            int m = p / 40, g = p - m * 40;
            const float2* Mr = Ms + m * 39;
            int ph = (21 * g) % 40;   // (-19*g) mod 40
            float re = 0.f, im = 0.f;
            #pragma unroll
            for (int nn = 0; nn < 39; nn++) {
                float2 tw = twl[ph];
                float2 mv = Mr[nn];
                re += mv.x * tw.x - mv.y * tw.y;
                im += mv.x * tw.y + mv.y * tw.x;
                ph += g;
                if (ph >= 40) ph -= 40;
            }
            Ts[p] = make_float2(re, im);
        }
        __syncthreads();
        // f[a,g] = T0[g].re + 2*sum_{m=1..19} Re(T[m,g] e^{+2pi i m a/40}) + bias
        for (int p = tid; p < 1600; p += blockDim.x) {
            int a = p / 40, g = p - a * 40;
            int ph = a;               // m=1 start
            float s = 0.f;
            #pragma unroll
            for (int m = 1; m < 20; m++) {
                float2 tw = twl[ph];
                float2 tv = Ts[m * 40 + g];
                s += tv.x * tw.x - tv.y * tw.y;
                ph += a;
                if (ph >= 40) ph -= 40;
            }
            outp[b * 1600 + p] = bv + Ts[g].x + 2.f * s;
        }
        __syncthreads();
    }
}

// ---------------- launcher ----------------
extern "C" void kernel_launch(void* const* d_in, const int* in_sizes, int n_in,
                              void* d_out, int out_size) {
    const float* x    = (const float*)d_in[0];   // [16,16,128,128]
    const float* ker  = (const float*)d_in[1];   // [16,32,24]
    const float* bias = (const float*)d_in[2];   // [32]
    float* out = (float*)d_out;                  // [16,32,40,40,40]

    cudaFuncSetAttribute(k_ZL,  cudaFuncAttributeMaxDynamicSharedMemorySize, 102400);
    cudaFuncSetAttribute(k_OUT, cudaFuncAttributeMaxDynamicSharedMemorySize, 57200);

    k_setup<<<1, 128>>>();
    k_ws2 <<<200, 256>>>();
    k_Fk  <<<38, 256>>>();
    k_dinv<<<(40 * NC + 255) / 256, 256>>>();
    k_XF  <<<256, 256>>>(x);
    k_G   <<<400, 256>>>();
    k_Y   <<<800, 256>>>(ker);
    k_ZL  <<<512, 256, 102400>>>();
    k_OUT <<<1024, 256, 57200>>>(bias, out);
}

// round 4
// speedup vs baseline: 1.5001x; 1.5001x over previous
#include <cuda_runtime.h>

#define PI_D 3.141592653589793238462643383279502884
#define SCALING_F 0.008164965809277260f   // 1/sqrt(24*16*20^4/64^2) = 1/sqrt(15000)

// Compact l-major layout for m>=0 spectra:
//   per l: (l+1) rows (m = 0..l) x (2l+1) cols (ni = n+l).  Total NC = 5530.
#define NC 5530

#define CMADD(acc, a, b) { acc.x += (a).x*(b).x - (a).y*(b).y; acc.y += (a).x*(b).y + (a).y*(b).x; }
#define CROT(w, s) { float _x = (w).x*(s).x - (w).y*(s).y; (w).y = (w).x*(s).y + (w).y*(s).x; (w).x = _x; }

// ---------------- scratch (device globals; no allocation allowed) ----------------
static __device__ double dd_df[41];                  // factorials
static __device__ double dd_wq[128];
static __device__ float  dd_ws2[128 * 400];          // [b][col]
static __device__ float2 dd_Fk[24 * 400];            // [p][col]
static __device__ float  dd_dinv[40 * NC];           // [b][cidx]  (2l+1)*d^l_{m,n}, m>=0
static __device__ float2 dd_XF[16 * 16 * 20 * 128];  // [(z*16+i)][m(0..19)][b]
static __device__ float2 dd_G[16 * 16 * 400];        // [(z*16+i)][col]
static __device__ float2 dd_Y[32 * 400 * 16];        // conj(y)*SCALING: [o][col][i]
static __device__ float2 dd_ZL[512 * NC];            // [(z*32+o)][cidx], m>=0 only
static __device__ float2 dd_tw40[40];                // e^{+2pi i t/40}
static __device__ float2 dd_tw128[128];              // e^{+2pi i t/128}

// ---------------- Wigner small-d via factorial-ratio recurrence (fp64) ----------------
__device__ double wigner_d_dev(int l, int m, int n, double beta) {
    double cb = cos(0.5 * beta), sb = sin(0.5 * beta);
    int s0 = (n - m) > 0 ? (n - m) : 0;
    int s1 = (l + n) < (l - m) ? (l + n) : (l - m);
    if (s1 < s0) return 0.0;
    double pref = sqrt(dd_df[l + m]) * sqrt(dd_df[l - m]) * sqrt(dd_df[l + n]) * sqrt(dd_df[l - n]);
    double t = pref / (dd_df[l + n - s0] * dd_df[s0] * dd_df[m - n + s0] * dd_df[l - m - s0]);
    int ec = 2 * l + n - m - 2 * s0;
    int es = m - n + 2 * s0;
    for (int k = 0; k < ec; k++) t *= cb;
    for (int k = 0; k < es; k++) t *= sb;
    if ((m - n + s0) & 1) t = -t;
    double v = t;
    double r2 = (sb * sb) / (cb * cb);
    for (int s = s0; s < s1; s++) {
        t *= -r2 * (double)((l + n - s) * (l - m - s)) / (double)((s + 1) * (m - n + s + 1));
        v += t;
    }
    return v;
}

__device__ __forceinline__ int col_to_l(int col) {
    int l = (int)sqrtf((float)col);
    while ((l + 1) * (l + 1) <= col) l++;
    while (l * l > col) l--;
    return l;
}

// decode compact cidx -> (l, m>=0, ni)
__device__ __forceinline__ void decode_c(int c, int& l, int& m, int& ni) {
    l = 0;
    while (c >= (l + 1) * (2 * l + 1)) { c -= (l + 1) * (2 * l + 1); l++; }
    int w = 2 * l + 1;
    m = c / w;
    ni = c - m * w;
}

// cum2(l) = sum_{j<l} (j+1)(2j+1)
__device__ __forceinline__ int cum2f(int l) {
    return (l - 1) * l * (2 * l - 1) / 3 + 3 * l * (l - 1) / 2 + l;
}

// ---------------- stage 0: tables ----------------
__global__ void k_setup() {
    int t = threadIdx.x;
    if (t < 41) {
        double f = 1.0;
        for (int k = 2; k <= t; k++) f *= (double)k;
        dd_df[t] = f;
    }
    if (t < 40) {
        double a = 2.0 * PI_D * t / 40.0;
        dd_tw40[t] = make_float2((float)cos(a), (float)sin(a));
    }
    if (t < 128) {
        double a = 2.0 * PI_D * t / 128.0;
        dd_tw128[t] = make_float2((float)cos(a), (float)sin(a));
        double th = PI_D * (2 * t + 1) / 256.0;
        double s = 0.0;
        for (int k = 0; k < 64; k++) s += sin((2.0 * k + 1.0) * th) / (2.0 * k + 1.0);
        dd_wq[t] = (2.0 / 64.0) * sin(th) * s;
    }
}

__global__ void k_ws2() {
    int idx = blockIdx.x * blockDim.x + threadIdx.x;
    if (idx >= 128 * 400) return;
    int b = idx / 400, col = idx - b * 400;
    int l = col_to_l(col);
    int m = col - l * l - l;
    double beta = PI_D * (2 * b + 1) / 256.0;
    dd_ws2[idx] = (float)(wigner_d_dev(l, m, 0, beta) * dd_wq[b]);
}

__global__ void k_Fk() {
    int idx = blockIdx.x * blockDim.x + threadIdx.x;
    if (idx >= 24 * 400) return;
    int p = idx / 400, col = idx - p * 400;
    int l = col_to_l(col);
    int m = col - l * l - l;
    double beta = (double)(p / 8 + 1) * PI_D / 24.0;
    double alpha = (double)(p % 8) * (PI_D / 4.0);
    double d = wigner_d_dev(l, m, 0, beta);
    dd_Fk[idx] = make_float2((float)(d * cos(m * alpha)), (float)(-d * sin(m * alpha)));
}

__global__ void k_dinv() {
    int idx = blockIdx.x * blockDim.x + threadIdx.x;
    if (idx >= 40 * NC) return;
    int b = idx / NC, c = idx - b * NC;
    int l, m, ni;
    decode_c(c, l, m, ni);
    double beta = PI_D * (2 * b + 1) / 80.0;
    dd_dinv[idx] = (float)((double)(2 * l + 1) * wigner_d_dev(l, m, ni - l, beta));
}

// ---------------- stage 1: alpha-DFT (20 non-negative bins), one block per (z,i) ----------------
__global__ void k_XF(const float* __restrict__ x) {
    __shared__ float2 twT[128 * 20];   // [a][m], e^{-2pi i m a/128} stored as (cos,-sin)
    __shared__ float  xs[12][129];     // padded rows
    int zi = blockIdx.x;
    int t = threadIdx.x;               // 256 threads
    for (int i = t; i < 128 * 20; i += 256) {
        int a = i / 20, mi = i - a * 20;
        float2 w = dd_tw128[(a * mi) & 127];
        twT[i] = make_float2(w.x, -w.y);
    }
    const float* xp = x + (size_t)zi * 128 * 128;
    for (int chunk = 0; chunk < 11; chunk++) {
        int b0 = chunk * 12;
        __syncthreads();
        for (int i = t; i < 12 * 128; i += 256) {
            int r = i >> 7, a = i & 127;
            if (b0 + r < 128) xs[r][a] = xp[(size_t)(b0 + r) * 128 + a];
        }
        __syncthreads();
        if (t < 240) {
            int r = t / 20, mi = t - r * 20;
            int b = b0 + r;
            if (b < 128) {
                float re = 0.f, im = 0.f;
                #pragma unroll 8
                for (int a = 0; a < 128; a++) {
                    float v = xs[r][a];
                    float2 w = twT[a * 20 + mi];
                    re += v * w.x;
                    im += v * w.y;
                }
                dd_XF[((size_t)zi * 20 + mi) * 128 + b] = make_float2(re, im);
            }
        }
    }
}

// ---------------- stage 2: S2 analysis (negative m via conjugate) ----------------
__global__ void k_G() {
    int idx = blockIdx.x * blockDim.x + threadIdx.x;
    if (idx >= 16 * 16 * 400) return;
    int zi = idx / 400, col = idx - zi * 400;
    int l = col_to_l(col);
    int m = col - l * l - l;
    int am = m < 0 ? -m : m;
    float sgn = m < 0 ? -1.f : 1.f;
    const float2* xf = &dd_XF[((size_t)zi * 20 + am) * 128];
    float re = 0.f, im = 0.f;
    #pragma unroll 4
    for (int b = 0; b < 128; b++) {
        float w = dd_ws2[b * 400 + col];
        float2 v = xf[b];
        re += w * v.x;
        im += w * v.y;
    }
    dd_G[idx] = make_float2(re, sgn * im);
}

// ---------------- stage 3: kernel spectrum (store conj * SCALING) ----------------
__global__ void k_Y(const float* __restrict__ ker) {
    int idx = blockIdx.x * blockDim.x + threadIdx.x;
    if (idx >= 32 * 400 * 16) return;
    int o = idx / 6400;
    int r = idx - o * 6400;
    int col = r / 16, i = r - col * 16;
    const float* kp = ker + ((size_t)i * 32 + o) * 24;
    float re = 0.f, im = 0.f;
    #pragma unroll
    for (int p = 0; p < 24; p++) {
        float2 f = dd_Fk[p * 400 + col];
        float kv = kp[p];
        re += kv * f.x;
        im += kv * f.y;
    }
    dd_Y[idx] = make_float2(SCALING_F * re, -SCALING_F * im);
}

// ---------------- stage 4: per-(z,o) SO(3) spectrum (m>=0 only) ----------------
__global__ void k_ZL() {
    extern __shared__ float2 smzl[];
    float2* Gs = smzl;            // 6400: [i][col] for this z
    float2* Ys = smzl + 6400;     // 6400: [col][i] for this o (already conj)
    int bi = blockIdx.x;
    int z = bi >> 5, o = bi & 31;
    int tid = threadIdx.x;
    for (int i = tid; i < 6400; i += blockDim.x) {
        Gs[i] = dd_G[z * 6400 + i];
        Ys[i] = dd_Y[o * 6400 + i];
    }
    __syncthreads();
    for (int cidx = tid; cidx < NC; cidx += blockDim.x) {
        int l, m, ni;
        decode_c(cidx, l, m, ni);
        int colm = l * l + l + m;      // m >= 0
        int coln = l * l + ni;
        float re = 0.f, im = 0.f;
        #pragma unroll
        for (int i = 0; i < 16; i++) {
            float2 a = Gs[i * 400 + colm];
            float2 yb = Ys[coln * 16 + i];
            re += a.x * yb.x - a.y * yb.y;
            im += a.x * yb.y + a.y * yb.x;
        }
        dd_ZL[(size_t)bi * NC + cidx] = make_float2(re, im);
    }
}

// ---------------- stage 5+6 fused: beta synthesis + Hermitian 2D inverse DFT ----------------
// grid = 512 (z,o) * 2 beta-halves. Register phasors, 2x2 tiling, g/a parity folding.
// SMEM: zls (NC) | Ms (4*20*41) | Ts (4*20*41) | twl (40)
__global__ void k_OUT(const float* __restrict__ bias, float* __restrict__ out) {
    extern __shared__ float2 sm[];
    float2* zls = sm;                       // 5530
    float2* Ms  = sm + NC;                  // 4*820 = 3280, row stride 41
    float2* Ts  = Ms + 4 * 820;             // 3280, row stride 41
    float2* twl = Ts + 4 * 820;             // 40
    int bi = blockIdx.x >> 1;
    int half = blockIdx.x & 1;
    int o = bi & 31;
    int tid = threadIdx.x;
    for (int i = tid; i < NC; i += 256) zls[i] = dd_ZL[(size_t)bi * NC + i];
    if (tid < 40) twl[tid] = dd_tw40[tid];
    float bv = bias[o];
    __syncthreads();
    float* outp = out + (size_t)bi * 64000;

    for (int chunk = 0; chunk < 5; chunk++) {
        int b0 = half * 20 + chunk * 4;
        // ---- M-stage: M[bl,m,nni] = sum_l zl[l,m,n]*dinv[l,b,m,n], m>=0 ----
        for (int p = tid; p < 4 * 780; p += 256) {
            int bl = p / 780, q = p - bl * 780;
            int m = q / 39, nni = q - m * 39;
            int n = nni - 19;
            int an = n < 0 ? -n : n;
            int lmin = m > an ? m : an;
            int cum = cum2f(lmin);
            const float* dv = &dd_dinv[(size_t)(b0 + bl) * NC];
            float re = 0.f, im = 0.f;
            for (int l = lmin; l < 20; l++) {
                int w = 2 * l + 1;
                int cidx = cum + m * w + (n + l);
                float d = dv[cidx];
                float2 zv = zls[cidx];
                re += zv.x * d;
                im += zv.y * d;
                cum += (l + 1) * w;
            }
            Ms[(bl * 20 + m) * 41 + nni] = make_float2(re, im);
        }
        __syncthreads();
        // ---- T-stage: T[m,g] = sum_n M[m,n] e^{+i n g th}; emit g and g+20 via n-parity ----
        // tiles: bl(4) x tm(10) x tg(10), each 2m x 2(g0)
        for (int tt = tid; tt < 400; tt += 256) {
            int bl = tt / 100, r = tt - bl * 100;
            int tm = r / 10, tg = r - tm * 10;
            int m0 = tm * 2, g0 = tg * 2;
            const float2* M0 = &Ms[(bl * 20 + m0) * 41];
            const float2* M1 = M0 + 41;
            float2 w0 = twl[(21 * g0) % 40];        // e^{i(-19)g0 th}
            float2 w1 = twl[(21 * (g0 + 1)) % 40];
            float2 s0 = twl[g0], s1 = twl[g0 + 1];
            float2 aE00 = {0,0}, aE01 = {0,0}, aE10 = {0,0}, aE11 = {0,0};
            float2 aO00 = {0,0}, aO01 = {0,0}, aO10 = {0,0}, aO11 = {0,0};
            #pragma unroll
            for (int nn = 0; nn < 39; nn++) {
                float2 mv0 = M0[nn], mv1 = M1[nn];
                if (nn & 1) {   // n = nn-19 even
                    CMADD(aE00, mv0, w0); CMADD(aE01, mv0, w1);
                    CMADD(aE10, mv1, w0); CMADD(aE11, mv1, w1);
                } else {        // n odd
                    CMADD(aO00, mv0, w0); CMADD(aO01, mv0, w1);
                    CMADD(aO10, mv1, w0); CMADD(aO11, mv1, w1);
                }
                CROT(w0, s0); CROT(w1, s1);
            }
            float2* T0 = &Ts[(bl * 20 + m0) * 41];
            float2* T1 = T0 + 41;
            T0[g0]      = make_float2(aE00.x + aO00.x, aE00.y + aO00.y);
            T0[g0 + 1]  = make_float2(aE01.x + aO01.x, aE01.y + aO01.y);
            T0[g0 + 20] = make_float2(aE00.x - aO00.x, aE00.y - aO00.y);
            T0[g0 + 21] = make_float2(aE01.x - aO01.x, aE01.y - aO01.y);
            T1[g0]      = make_float2(aE10.x + aO10.x, aE10.y + aO10.y);
            T1[g0 + 1]  = make_float2(aE11.x + aO11.x, aE11.y + aO11.y);
            T1[g0 + 20] = make_float2(aE10.x - aO10.x, aE10.y - aO10.y);
            T1[g0 + 21] = make_float2(aE11.x - aO11.x, aE11.y - aO11.y);
        }
        __syncthreads();
        // ---- f-stage: f[a,g] = bv + T[0,g].re + 2 sum_{m>=1} Re(T[m,g] e^{i m a th});
        //      emit a and a+20 via m-parity. tiles: bl(4) x ta(10) x tg(20), each 2a x 2g
        for (int tt = tid; tt < 800; tt += 256) {
            int bl = tt / 200, r = tt - bl * 200;
            int ta = r / 20, tg = r - ta * 20;
            int a0 = ta * 2, g0 = tg * 2;
            const float2* Tb = &Ts[(bl * 20) * 41];
            float2 w0 = twl[a0], w1 = twl[a0 + 1];   // m=1 phase
            float2 s0 = w0, s1 = w1;
            float sE00 = 0.f, sE01 = 0.f, sE10 = 0.f, sE11 = 0.f;
            float sO00 = 0.f, sO01 = 0.f, sO10 = 0.f, sO11 = 0.f;
            #pragma unroll
            for (int m = 1; m < 20; m++) {
                float2 t0 = Tb[m * 41 + g0];
                float2 t1 = Tb[m * 41 + g0 + 1];
                float v00 = t0.x * w0.x - t0.y * w0.y;
                float v01 = t1.x * w0.x - t1.y * w0.y;
                float v10 = t0.x * w1.x - t0.y * w1.y;
                float v11 = t1.x * w1.x - t1.y * w1.y;
                if (m & 1) { sO00 += v00; sO01 += v01; sO10 += v10; sO11 += v11; }
                else       { sE00 += v00; sE01 += v01; sE10 += v10; sE11 += v11; }
                CROT(w0, s0); CROT(w1, s1);
            }
            float base0 = bv + Tb[g0].x;
            float base1 = bv + Tb[g0 + 1].x;
            float* op = outp + (size_t)(b0 + bl) * 1600;
            *(float2*)&op[a0 * 40 + g0] =
                make_float2(base0 + 2.f * (sE00 + sO00), base1 + 2.f * (sE01 + sO01));
            *(float2*)&op[(a0 + 1) * 40 + g0] =
                make_float2(base0 + 2.f * (sE10 + sO10), base1 + 2.f * (sE11 + sO11));
            *(float2*)&op[(a0 + 20) * 40 + g0] =
                make_float2(base0 + 2.f * (sE00 - sO00), base1 + 2.f * (sE01 - sO01));
            *(float2*)&op[(a0 + 21) * 40 + g0] =
                make_float2(base0 + 2.f * (sE10 - sO10), base1 + 2.f * (sE11 - sO11));
        }
        __syncthreads();
    }
}

// ---------------- launcher ----------------
extern "C" void kernel_launch(void* const* d_in, const int* in_sizes, int n_in,
                              void* d_out, int out_size) {
    const float* x    = (const float*)d_in[0];   // [16,16,128,128]
    const float* ker  = (const float*)d_in[1];   // [16,32,24]
    const float* bias = (const float*)d_in[2];   // [32]
    float* out = (float*)d_out;                  // [16,32,40,40,40]

    cudaFuncSetAttribute(k_ZL,  cudaFuncAttributeMaxDynamicSharedMemorySize, 102400);
    cudaFuncSetAttribute(k_OUT, cudaFuncAttributeMaxDynamicSharedMemorySize, 97600);

    k_setup<<<1, 128>>>();
    k_ws2 <<<200, 256>>>();
    k_Fk  <<<38, 256>>>();
    k_dinv<<<(40 * NC + 255) / 256, 256>>>();
    k_XF  <<<256, 256>>>(x);
    k_G   <<<400, 256>>>();
    k_Y   <<<800, 256>>>(ker);
    k_ZL  <<<512, 256, 102400>>>();
    k_OUT <<<1024, 256, 97600>>>(bias, out);
}

// round 5
// speedup vs baseline: 1.7468x; 1.1645x over previous
#include <cuda_runtime.h>

#define PI_D 3.141592653589793238462643383279502884
#define SCALING_F 0.008164965809277260f   // 1/sqrt(24*16*20^4/64^2) = 1/sqrt(15000)

// Compact l-major layout for m>=0 spectra:
//   per l: (l+1) rows (m = 0..l) x (2l+1) cols (ni = n+l).  Total NC = 5530.
#define NC 5530

#define CMADD(acc, a, b) { acc.x += (a).x*(b).x - (a).y*(b).y; acc.y += (a).x*(b).y + (a).y*(b).x; }
#define CROT(w, s) { float _x = (w).x*(s).x - (w).y*(s).y; (w).y = (w).x*(s).y + (w).y*(s).x; (w).x = _x; }

// ---------------- scratch (device globals; no allocation allowed) ----------------
static __device__ double dd_df[41];                  // factorials
static __device__ double dd_wq[128];
static __device__ float  dd_ws2[128 * 400];          // [b][col]
static __device__ float2 dd_Fk[24 * 400];            // [p][col]
static __device__ float  dd_dinv[40 * NC];           // [b][cidx]  (2l+1)*d^l_{m,n}, m>=0
static __device__ float2 dd_XF[16 * 16 * 20 * 128];  // [(z*16+i)][m(0..19)][b]
static __device__ float2 dd_G[16 * 16 * 400];        // [(z*16+i)][col]
static __device__ float2 dd_Y[32 * 16 * 400];        // conj(y)*SCALING: [o][i][col]  (i-major!)
static __device__ float2 dd_ZL[512 * NC];            // [(z*32+o)][cidx], m>=0 only
static __device__ float2 dd_tw40[40];                // e^{+2pi i t/40}
static __device__ float2 dd_tw128[128];              // e^{+2pi i t/128}

// ---------------- Wigner small-d via factorial-ratio recurrence (fp64) ----------------
__device__ double wigner_d_dev(int l, int m, int n, double beta) {
    double cb = cos(0.5 * beta), sb = sin(0.5 * beta);
    int s0 = (n - m) > 0 ? (n - m) : 0;
    int s1 = (l + n) < (l - m) ? (l + n) : (l - m);
    if (s1 < s0) return 0.0;
    double pref = sqrt(dd_df[l + m]) * sqrt(dd_df[l - m]) * sqrt(dd_df[l + n]) * sqrt(dd_df[l - n]);
    double t = pref / (dd_df[l + n - s0] * dd_df[s0] * dd_df[m - n + s0] * dd_df[l - m - s0]);
    int ec = 2 * l + n - m - 2 * s0;
    int es = m - n + 2 * s0;
    for (int k = 0; k < ec; k++) t *= cb;
    for (int k = 0; k < es; k++) t *= sb;
    if ((m - n + s0) & 1) t = -t;
    double v = t;
    double r2 = (sb * sb) / (cb * cb);
    for (int s = s0; s < s1; s++) {
        t *= -r2 * (double)((l + n - s) * (l - m - s)) / (double)((s + 1) * (m - n + s + 1));
        v += t;
    }
    return v;
}

__device__ __forceinline__ int col_to_l(int col) {
    int l = (int)sqrtf((float)col);
    while ((l + 1) * (l + 1) <= col) l++;
    while (l * l > col) l--;
    return l;
}

// decode compact cidx -> (l, m>=0, ni)
__device__ __forceinline__ void decode_c(int c, int& l, int& m, int& ni) {
    l = 0;
    while (c >= (l + 1) * (2 * l + 1)) { c -= (l + 1) * (2 * l + 1); l++; }
    int w = 2 * l + 1;
    m = c / w;
    ni = c - m * w;
}

// cum2(l) = sum_{j<l} (j+1)(2j+1)
__device__ __forceinline__ int cum2f(int l) {
    return (l - 1) * l * (2 * l - 1) / 3 + 3 * l * (l - 1) / 2 + l;
}

// ---------------- stage 0: tables ----------------
__global__ void k_setup() {
    int t = threadIdx.x;
    if (t < 41) {
        double f = 1.0;
        for (int k = 2; k <= t; k++) f *= (double)k;
        dd_df[t] = f;
    }
    if (t < 40) {
        double a = 2.0 * PI_D * t / 40.0;
        dd_tw40[t] = make_float2((float)cos(a), (float)sin(a));
    }
    if (t < 128) {
        double a = 2.0 * PI_D * t / 128.0;
        dd_tw128[t] = make_float2((float)cos(a), (float)sin(a));
        double th = PI_D * (2 * t + 1) / 256.0;
        double s = 0.0;
        for (int k = 0; k < 64; k++) s += sin((2.0 * k + 1.0) * th) / (2.0 * k + 1.0);
        dd_wq[t] = (2.0 / 64.0) * sin(th) * s;
    }
}

__global__ void k_ws2() {
    int idx = blockIdx.x * blockDim.x + threadIdx.x;
    if (idx >= 128 * 400) return;
    int b = idx / 400, col = idx - b * 400;
    int l = col_to_l(col);
    int m = col - l * l - l;
    double beta = PI_D * (2 * b + 1) / 256.0;
    dd_ws2[idx] = (float)(wigner_d_dev(l, m, 0, beta) * dd_wq[b]);
}

__global__ void k_Fk() {
    int idx = blockIdx.x * blockDim.x + threadIdx.x;
    if (idx >= 24 * 400) return;
    int p = idx / 400, col = idx - p * 400;
    int l = col_to_l(col);
    int m = col - l * l - l;
    double beta = (double)(p / 8 + 1) * PI_D / 24.0;
    double alpha = (double)(p % 8) * (PI_D / 4.0);
    double d = wigner_d_dev(l, m, 0, beta);
    dd_Fk[idx] = make_float2((float)(d * cos(m * alpha)), (float)(-d * sin(m * alpha)));
}

__global__ void k_dinv() {
    int idx = blockIdx.x * blockDim.x + threadIdx.x;
    if (idx >= 40 * NC) return;
    int b = idx / NC, c = idx - b * NC;
    int l, m, ni;
    decode_c(c, l, m, ni);
    double beta = PI_D * (2 * b + 1) / 80.0;
    dd_dinv[idx] = (float)((double)(2 * l + 1) * wigner_d_dev(l, m, ni - l, beta));
}

// ---------------- stage 1: alpha-DFT (20 non-negative bins), one block per (z,i) ----------------
__global__ void k_XF(const float* __restrict__ x) {
    __shared__ float2 twT[128 * 20];   // [a][m], e^{-2pi i m a/128} stored as (cos,-sin)
    __shared__ float  xs[12][129];     // padded rows
    int zi = blockIdx.x;
    int t = threadIdx.x;               // 256 threads
    for (int i = t; i < 128 * 20; i += 256) {
        int a = i / 20, mi = i - a * 20;
        float2 w = dd_tw128[(a * mi) & 127];
        twT[i] = make_float2(w.x, -w.y);
    }
    const float* xp = x + (size_t)zi * 128 * 128;
    for (int chunk = 0; chunk < 11; chunk++) {
        int b0 = chunk * 12;
        __syncthreads();
        for (int i = t; i < 12 * 128; i += 256) {
            int r = i >> 7, a = i & 127;
            if (b0 + r < 128) xs[r][a] = xp[(size_t)(b0 + r) * 128 + a];
        }
        __syncthreads();
        if (t < 240) {
            int r = t / 20, mi = t - r * 20;
            int b = b0 + r;
            if (b < 128) {
                float re = 0.f, im = 0.f;
                #pragma unroll 8
                for (int a = 0; a < 128; a++) {
                    float v = xs[r][a];
                    float2 w = twT[a * 20 + mi];
                    re += v * w.x;
                    im += v * w.y;
                }
                dd_XF[((size_t)zi * 20 + mi) * 128 + b] = make_float2(re, im);
            }
        }
    }
}

// ---------------- stage 2: S2 analysis (negative m via conjugate) ----------------
__global__ void k_G() {
    int idx = blockIdx.x * blockDim.x + threadIdx.x;
    if (idx >= 16 * 16 * 400) return;
    int zi = idx / 400, col = idx - zi * 400;
    int l = col_to_l(col);
    int m = col - l * l - l;
    int am = m < 0 ? -m : m;
    float sgn = m < 0 ? -1.f : 1.f;
    const float2* xf = &dd_XF[((size_t)zi * 20 + am) * 128];
    float re = 0.f, im = 0.f;
    #pragma unroll 4
    for (int b = 0; b < 128; b++) {
        float w = dd_ws2[b * 400 + col];
        float2 v = xf[b];
        re += w * v.x;
        im += w * v.y;
    }
    dd_G[idx] = make_float2(re, sgn * im);
}

// ---------------- stage 3: kernel spectrum (store conj * SCALING), i-major layout ----------------
__global__ void k_Y(const float* __restrict__ ker) {
    int idx = blockIdx.x * blockDim.x + threadIdx.x;
    if (idx >= 32 * 16 * 400) return;
    int o = idx / 6400;
    int r = idx - o * 6400;
    int i = r / 400, col = r - i * 400;
    const float* kp = ker + ((size_t)i * 32 + o) * 24;
    float re = 0.f, im = 0.f;
    #pragma unroll
    for (int p = 0; p < 24; p++) {
        float2 f = dd_Fk[p * 400 + col];
        float kv = kp[p];
        re += kv * f.x;
        im += kv * f.y;
    }
    dd_Y[idx] = make_float2(SCALING_F * re, -SCALING_F * im);
}

// ---------------- stage 4: per-(z,o) SO(3) spectrum (m>=0 only) ----------------
__global__ void k_ZL() {
    extern __shared__ float2 smzl[];
    float2* Gs = smzl;            // 6400: [i][col] for this z
    float2* Ys = smzl + 6400;     // 6400: [i][col] for this o (already conj) — conflict-free
    int bi = blockIdx.x;
    int z = bi >> 5, o = bi & 31;
    int tid = threadIdx.x;
    for (int i = tid; i < 6400; i += blockDim.x) {
        Gs[i] = dd_G[z * 6400 + i];
        Ys[i] = dd_Y[o * 6400 + i];
    }
    __syncthreads();
    for (int cidx = tid; cidx < NC; cidx += blockDim.x) {
        int l, m, ni;
        decode_c(cidx, l, m, ni);
        int colm = l * l + l + m;      // m >= 0
        int coln = l * l + ni;
        float re = 0.f, im = 0.f;
        #pragma unroll
        for (int i = 0; i < 16; i++) {
            float2 a = Gs[i * 400 + colm];
            float2 yb = Ys[i * 400 + coln];
            re += a.x * yb.x - a.y * yb.y;
            im += a.x * yb.y + a.y * yb.x;
        }
        dd_ZL[(size_t)bi * NC + cidx] = make_float2(re, im);
    }
}

// ---------------- stage 5+6 fused: beta synthesis + Hermitian 2D inverse DFT ----------------
// grid = 512 (z,o) * 4 beta-quarters, 2 betas per chunk. Register phasors, 2x2 tiling,
// g/a parity folding. SMEM: zls (NC) | Ms (2*820) | Ts (2*820) | twl (40) = 70800 B.
__global__ void k_OUT(const float* __restrict__ bias, float* __restrict__ out) {
    extern __shared__ float2 sm[];
    float2* zls = sm;                       // 5530
    float2* Ms  = sm + NC;                  // 2*820 = 1640, row stride 41
    float2* Ts  = Ms + 2 * 820;             // 1640, row stride 41
    float2* twl = Ts + 2 * 820;             // 40
    int bi = blockIdx.x >> 2;
    int quarter = blockIdx.x & 3;
    int o = bi & 31;
    int tid = threadIdx.x;
    for (int i = tid; i < NC; i += 256) zls[i] = dd_ZL[(size_t)bi * NC + i];
    if (tid < 40) twl[tid] = dd_tw40[tid];
    float bv = bias[o];
    __syncthreads();
    float* outp = out + (size_t)bi * 64000;

    for (int chunk = 0; chunk < 5; chunk++) {
        int b0 = quarter * 10 + chunk * 2;
        // ---- M-stage: M[bl,m,nni] = sum_l zl[l,m,n]*dinv[l,b,m,n], m>=0 ----
        for (int p = tid; p < 2 * 780; p += 256) {
            int bl = p / 780, q = p - bl * 780;
            int m = q / 39, nni = q - m * 39;
            int n = nni - 19;
            int an = n < 0 ? -n : n;
            int lmin = m > an ? m : an;
            int cum = cum2f(lmin);
            const float* dv = &dd_dinv[(size_t)(b0 + bl) * NC];
            float re = 0.f, im = 0.f;
            for (int l = lmin; l < 20; l++) {
                int w = 2 * l + 1;
                int cidx = cum + m * w + (n + l);
                float d = dv[cidx];
                float2 zv = zls[cidx];
                re += zv.x * d;
                im += zv.y * d;
                cum += (l + 1) * w;
            }
            Ms[(bl * 20 + m) * 41 + nni] = make_float2(re, im);
        }
        __syncthreads();
        // ---- T-stage: T[m,g] = sum_n M[m,n] e^{+i n g th}; emit g and g+20 via n-parity ----
        // tiles: bl(2) x tm(10) x tg(10), each 2m x 2(g0)
        for (int tt = tid; tt < 200; tt += 256) {
            int bl = tt / 100, r = tt - bl * 100;
            int tm = r / 10, tg = r - tm * 10;
            int m0 = tm * 2, g0 = tg * 2;
            const float2* M0 = &Ms[(bl * 20 + m0) * 41];
            const float2* M1 = M0 + 41;
            float2 w0 = twl[(21 * g0) % 40];        // e^{i(-19)g0 th}
            float2 w1 = twl[(21 * (g0 + 1)) % 40];
            float2 s0 = twl[g0], s1 = twl[g0 + 1];
            float2 aE00 = {0,0}, aE01 = {0,0}, aE10 = {0,0}, aE11 = {0,0};
            float2 aO00 = {0,0}, aO01 = {0,0}, aO10 = {0,0}, aO11 = {0,0};
            #pragma unroll
            for (int nn = 0; nn < 39; nn++) {
                float2 mv0 = M0[nn], mv1 = M1[nn];
                if (nn & 1) {   // n = nn-19 even
                    CMADD(aE00, mv0, w0); CMADD(aE01, mv0, w1);
                    CMADD(aE10, mv1, w0); CMADD(aE11, mv1, w1);
                } else {        // n odd
                    CMADD(aO00, mv0, w0); CMADD(aO01, mv0, w1);
                    CMADD(aO10, mv1, w0); CMADD(aO11, mv1, w1);
                }
                CROT(w0, s0); CROT(w1, s1);
            }
            float2* T0 = &Ts[(bl * 20 + m0) * 41];
            float2* T1 = T0 + 41;
            T0[g0]      = make_float2(aE00.x + aO00.x, aE00.y + aO00.y);
            T0[g0 + 1]  = make_float2(aE01.x + aO01.x, aE01.y + aO01.y);
            T0[g0 + 20] = make_float2(aE00.x - aO00.x, aE00.y - aO00.y);
            T0[g0 + 21] = make_float2(aE01.x - aO01.x, aE01.y - aO01.y);
            T1[g0]      = make_float2(aE10.x + aO10.x, aE10.y + aO10.y);
            T1[g0 + 1]  = make_float2(aE11.x + aO11.x, aE11.y + aO11.y);
            T1[g0 + 20] = make_float2(aE10.x - aO10.x, aE10.y - aO10.y);
            T1[g0 + 21] = make_float2(aE11.x - aO11.x, aE11.y - aO11.y);
        }
        __syncthreads();
        // ---- f-stage: f[a,g] = bv + T[0,g].re + 2 sum_{m>=1} Re(T[m,g] e^{i m a th});
        //      emit a and a+20 via m-parity. tiles: bl(2) x ta(10) x tg(20), each 2a x 2g
        for (int tt = tid; tt < 400; tt += 256) {
            int bl = tt / 200, r = tt - bl * 200;
            int ta = r / 20, tg = r - ta * 20;
            int a0 = ta * 2, g0 = tg * 2;
            const float2* Tb = &Ts[(bl * 20) * 41];
            float2 w0 = twl[a0], w1 = twl[a0 + 1];   // m=1 phase
            float2 s0 = w0, s1 = w1;
            float sE00 = 0.f, sE01 = 0.f, sE10 = 0.f, sE11 = 0.f;
            float sO00 = 0.f, sO01 = 0.f, sO10 = 0.f, sO11 = 0.f;
            #pragma unroll
            for (int m = 1; m < 20; m++) {
                float2 t0 = Tb[m * 41 + g0];
                float2 t1 = Tb[m * 41 + g0 + 1];
                float v00 = t0.x * w0.x - t0.y * w0.y;
                float v01 = t1.x * w0.x - t1.y * w0.y;
                float v10 = t0.x * w1.x - t0.y * w1.y;
                float v11 = t1.x * w1.x - t1.y * w1.y;
                if (m & 1) { sO00 += v00; sO01 += v01; sO10 += v10; sO11 += v11; }
                else       { sE00 += v00; sE01 += v01; sE10 += v10; sE11 += v11; }
                CROT(w0, s0); CROT(w1, s1);
            }
            float base0 = bv + Tb[g0].x;
            float base1 = bv + Tb[g0 + 1].x;
            float* op = outp + (size_t)(b0 + bl) * 1600;
            *(float2*)&op[a0 * 40 + g0] =
                make_float2(base0 + 2.f * (sE00 + sO00), base1 + 2.f * (sE01 + sO01));
            *(float2*)&op[(a0 + 1) * 40 + g0] =
                make_float2(base0 + 2.f * (sE10 + sO10), base1 + 2.f * (sE11 + sO11));
            *(float2*)&op[(a0 + 20) * 40 + g0] =
                make_float2(base0 + 2.f * (sE00 - sO00), base1 + 2.f * (sE01 - sO01));
            *(float2*)&op[(a0 + 21) * 40 + g0] =
                make_float2(base0 + 2.f * (sE10 - sO10), base1 + 2.f * (sE11 - sO11));
        }
        __syncthreads();
    }
}

// ---------------- launcher ----------------
extern "C" void kernel_launch(void* const* d_in, const int* in_sizes, int n_in,
                              void* d_out, int out_size) {
    const float* x    = (const float*)d_in[0];   // [16,16,128,128]
    const float* ker  = (const float*)d_in[1];   // [16,32,24]
    const float* bias = (const float*)d_in[2];   // [32]
    float* out = (float*)d_out;                  // [16,32,40,40,40]

    cudaFuncSetAttribute(k_ZL,  cudaFuncAttributeMaxDynamicSharedMemorySize, 102400);
    cudaFuncSetAttribute(k_OUT, cudaFuncAttributeMaxDynamicSharedMemorySize, 70800);

    k_setup<<<1, 128>>>();
    k_ws2 <<<200, 256>>>();
    k_Fk  <<<38, 256>>>();
    k_dinv<<<(40 * NC + 255) / 256, 256>>>();
    k_XF  <<<256, 256>>>(x);
    k_G   <<<400, 256>>>();
    k_Y   <<<800, 256>>>(ker);
    k_ZL  <<<512, 256, 102400>>>();
    k_OUT <<<2048, 256, 70800>>>(bias, out);
}